// round 12
// baseline (speedup 1.0000x reference)
#include <cuda_runtime.h>
#include <math.h>
#include <stdint.h>

// Problem constants (match reference_code)
#define N_HITS 200000
#define DIM 8
#define P_IDS 512
#define NCLUST 511          // nonzero particle ids 1..511
#define NPAIR 256           // 512 clusters (1 dummy pad) as 256 packed pairs
#define Q_MIN 0.01f

// ---------------------------------------------------------------------------
// Device scratch (no allocations allowed -> __device__ globals)
// ---------------------------------------------------------------------------
__device__ double g_sum;                           // static-init 0
__device__ unsigned long long g_best[P_IDS];       // packed (q_bits<<32)|(~idx)
__device__ int g_done_a;                           // block counter (argmax)
__device__ int g_done_m;                           // block counter (main)
// Pair-packed coefficients: pair j (clusters 2j, 2j+1), stride 20 floats:
//   float j*20 + 2*k + h : k=0..7 -> -2*xa_k ; k=8 -> |xa|^2 ; 18..19 unused
__device__ __align__(16) float g_pairc[NPAIR * 20];
__device__ float g_qa[P_IDS];                      // q_alpha per cluster (pad=0)

// ---------------------------------------------------------------------------
// Packed f32x2 helpers (sm_100+)
// ---------------------------------------------------------------------------
typedef unsigned long long u64;
__device__ __forceinline__ u64 fma2(u64 a, u64 b, u64 c) {
    u64 d;
    asm("fma.rn.f32x2 %0, %1, %2, %3;" : "=l"(d) : "l"(a), "l"(b), "l"(c));
    return d;
}
__device__ __forceinline__ u64 add2(u64 a, u64 b) {
    u64 d;
    asm("add.rn.f32x2 %0, %1, %2;" : "=l"(d) : "l"(a), "l"(b));
    return d;
}
__device__ __forceinline__ u64 bcast2(float x) {
    u64 r;
    asm("mov.b64 %0, {%1, %2};" : "=l"(r) : "f"(x), "f"(x));
    return r;
}
__device__ __forceinline__ float lo2(u64 v) {
    float lo, hi;
    asm("mov.b64 {%0, %1}, %2;" : "=f"(lo), "=f"(hi) : "l"(v));
    return lo;
}
__device__ __forceinline__ u64 dbits(double d) { return __double_as_longlong(d); }

// Fast atanh: 0.5*ln((1+b)/(1-b)) via MUFU.LG2 + MUFU.RCP.
// beta in [0,1); rel err ~1e-6 -- far below the 1e-3 test threshold.
__device__ __forceinline__ float compute_q(float beta) {
    float r = __fdividef(1.0f + beta, 1.0f - beta);
    float a = 0.5f * __logf(r);
    return fmaf(a, a, Q_MIN);
}

// ---------------------------------------------------------------------------
// Kernel 1: per-cluster argmax of q. Two-stage: shared-memory atomicMax
// pre-aggregation per block, then one global atomicMax per touched cluster.
// The LAST block performs the representative gather (launch fusion).
// q >= 0.01 > 0 so float bits are monotone as unsigned; index complemented so
// q-ties pick the LOWER index (matches jnp.argmax). g_best==0 on entry
// (static init; re-zeroed in the gather phase each run).
// ---------------------------------------------------------------------------
#define ATPB 1024

__global__ __launch_bounds__(ATPB) void k_argmax(const float* __restrict__ beta,
                                                 const int* __restrict__ pid,
                                                 const float* __restrict__ x) {
    __shared__ unsigned long long s_best[P_IDS];      // 4 KB
    if (threadIdx.x < P_IDS) s_best[threadIdx.x] = 0ull;
    __syncthreads();

    int i = blockIdx.x * ATPB + threadIdx.x;
    if (i < N_HITS) {
        int p = pid[i];
        if (p != 0) {
            float q = compute_q(beta[i]);
            u64 packed = ((u64)__float_as_uint(q) << 32) |
                         (u64)(0xFFFFFFFFu - (unsigned)i);
            atomicMax(&s_best[p], packed);
        }
    }
    __syncthreads();

    // Flush touched clusters to global
    if (threadIdx.x > 0 && threadIdx.x < P_IDS) {
        u64 v = s_best[threadIdx.x];
        if (v != 0ull) atomicMax(&g_best[threadIdx.x], v);
    }

    // ---- last-block gather ----
    __threadfence();
    __syncthreads();
    __shared__ int s_last;
    if (threadIdx.x == 0)
        s_last = (atomicAdd(&g_done_a, 1) == (int)gridDim.x - 1);
    __syncthreads();
    if (!s_last) return;
    __threadfence();                                  // acquire

    if (threadIdx.x < P_IDS) {
        int p = threadIdx.x;                          // cluster idx 0..511
        int j = p >> 1, h = p & 1;
        float* dst = g_pairc + j * 20;
        if (p == NCLUST) {                            // dummy pad cluster
#pragma unroll
            for (int k = 0; k < 8; k++) dst[2 * k + h] = 0.f;
            dst[16 + h] = 1e30f;                      // huge b -> hinge never
            g_qa[p] = 0.f;
        } else {
            u64 packed = g_best[p + 1];
            g_best[p + 1] = 0ull;                     // reset for next replay
            int idx = (packed == 0ull)
                          ? 0
                          : (int)(0xFFFFFFFFu - (unsigned)(packed & 0xFFFFFFFFull));
            float b = 0.f;
#pragma unroll
            for (int k = 0; k < DIM; k++) {
                float v = x[idx * DIM + k];
                dst[2 * k + h] = -2.f * v;
                b = fmaf(v, v, b);
            }
            dst[16 + h] = b;
            g_qa[p] = compute_q(beta[idx]);
        }
    }
    if (threadIdx.x == 0) g_done_a = 0;               // reset counter
}

// ---------------------------------------------------------------------------
// Kernel 2: main loop. Grid = (hit groups) x (8 cluster eighths). R10 lesson:
// k_main pinned ~50us across occ 44-75% with fma-busy exactly matching the
// rt-2 FFMA2 work -> the other half was the per-iteration if's BSSY/BSYNC
// envelope (~35cyc/iter). This version is BRANCH-FREE in the hot loop:
// d[h] = (t - thr[h]) packed; sign bits OR'd into one u64 flag. After the
// loop, threads with any sign bit set (~1%) rescan their 64 clusters with
// identical scalar fmaf chains (same rounding) to accumulate hinge terms.
// Own-cluster fixup only in the owning eighth. LAST block finalizes.
// ---------------------------------------------------------------------------
#define TPB 128
#define NH 2
#define HPB (TPB * NH)          // 256 hits per group
#define NGRP ((N_HITS + HPB - 1) / HPB)   // 782
#define NSPLIT 8                // cluster eighths
#define PPH (NPAIR / NSPLIT)    // 32 pairs per eighth
#define CPH (P_IDS / NSPLIT)    // 64 clusters per eighth
#define SIGNS 0x8000000080000000ull

__global__ __launch_bounds__(TPB) void k_main(const float* __restrict__ beta,
                                              const float* __restrict__ x,
                                              const int* __restrict__ pid,
                                              float* __restrict__ out) {
    __shared__ __align__(16) float s_c[PPH * 20];     // 2560 B
    __shared__ float s_q[CPH];                        // 256 B

    int grp = blockIdx.x >> 3;
    int hc  = blockIdx.x & 7;                         // cluster eighth 0..7
    {
        const float4* src = (const float4*)(g_pairc + hc * PPH * 20);
        float4* dst = (float4*)s_c;
        for (int t = threadIdx.x; t < PPH * 5; t += TPB) dst[t] = src[t];
        if (threadIdx.x < CPH) s_q[threadIdx.x] = g_qa[hc * CPH + threadIdx.x];
    }
    __syncthreads();

    int ibase = grp * HPB + threadIdx.x;
    float xsq[NH], thr[NH];
    u64 X[NH][8];     // broadcast-packed coords
    u64 NT[NH];       // broadcast-packed (-thr)
#pragma unroll
    for (int h = 0; h < NH; h++) {
        int i = ibase + h * TPB;
        int ic = i < N_HITS ? i : N_HITS - 1;         // clamp tail
        float4 v0 = *(const float4*)(x + (size_t)ic * DIM);
        float4 v1 = *(const float4*)(x + (size_t)ic * DIM + 4);
        float s = v0.x * v0.x + v0.y * v0.y + v0.z * v0.z + v0.w * v0.w
                + v1.x * v1.x + v1.y * v1.y + v1.z * v1.z + v1.w * v1.w;
        xsq[h] = s;
        thr[h] = 1.0f - s;
        NT[h] = bcast2(-thr[h]);
        X[h][0] = bcast2(v0.x); X[h][1] = bcast2(v0.y);
        X[h][2] = bcast2(v0.z); X[h][3] = bcast2(v0.w);
        X[h][4] = bcast2(v1.x); X[h][5] = bcast2(v1.y);
        X[h][6] = bcast2(v1.z); X[h][7] = bcast2(v1.w);
    }

    // ---- branch-free hot loop: only a sign-bit flag escapes ----
    u64 flag = 0ull;
#pragma unroll 4
    for (int j = 0; j < PPH; j++) {
        const float* base = s_c + j * 20;
        double2 c01 = *(const double2*)(base);
        double2 c23 = *(const double2*)(base + 4);
        double2 c45 = *(const double2*)(base + 8);
        double2 c67 = *(const double2*)(base + 12);
        u64 bp = *(const u64*)(base + 16);

        u64 acc[NH];
#pragma unroll
        for (int h = 0; h < NH; h++) acc[h] = fma2(dbits(c01.x), X[h][0], bp);
#pragma unroll
        for (int h = 0; h < NH; h++) acc[h] = fma2(dbits(c01.y), X[h][1], acc[h]);
#pragma unroll
        for (int h = 0; h < NH; h++) acc[h] = fma2(dbits(c23.x), X[h][2], acc[h]);
#pragma unroll
        for (int h = 0; h < NH; h++) acc[h] = fma2(dbits(c23.y), X[h][3], acc[h]);
#pragma unroll
        for (int h = 0; h < NH; h++) acc[h] = fma2(dbits(c45.x), X[h][4], acc[h]);
#pragma unroll
        for (int h = 0; h < NH; h++) acc[h] = fma2(dbits(c45.y), X[h][5], acc[h]);
#pragma unroll
        for (int h = 0; h < NH; h++) acc[h] = fma2(dbits(c67.x), X[h][6], acc[h]);
#pragma unroll
        for (int h = 0; h < NH; h++) acc[h] = fma2(dbits(c67.y), X[h][7], acc[h]);

        // d = t - thr ; sign bit set <=> t < thr <=> dist^2 < 1 (hinge active)
        u64 d0 = add2(acc[0], NT[0]);
        u64 d1 = add2(acc[1], NT[1]);
        flag |= d0 | d1;
    }

    // ---- rare rescan: ~1% of threads have any hinge-active cluster ----
    float rsum[NH];
#pragma unroll
    for (int h = 0; h < NH; h++) rsum[h] = 0.f;
    if (flag & SIGNS) {
#pragma unroll 1
        for (int p = 0; p < CPH; p++) {
            const float* cf = s_c + (p >> 1) * 20 + (p & 1);
            float qa = s_q[p];
            float b = cf[16];
#pragma unroll
            for (int h = 0; h < NH; h++) {
                float t = b;   // identical fmaf chain as fma2 lanes -> same rounding
                t = fmaf(cf[0],  lo2(X[h][0]), t);
                t = fmaf(cf[2],  lo2(X[h][1]), t);
                t = fmaf(cf[4],  lo2(X[h][2]), t);
                t = fmaf(cf[6],  lo2(X[h][3]), t);
                t = fmaf(cf[8],  lo2(X[h][4]), t);
                t = fmaf(cf[10], lo2(X[h][5]), t);
                t = fmaf(cf[12], lo2(X[h][6]), t);
                t = fmaf(cf[14], lo2(X[h][7]), t);
                if (t < thr[h]) {
                    float d2 = fmaxf(xsq[h] + t, 0.f);
                    rsum[h] = fmaf(1.0f - sqrtf(fmaxf(d2, 1e-12f)), qa, rsum[h]);
                }
            }
        }
    }

    // Per-hit q / pid loaded AFTER the hot loop (lower live-reg pressure)
    double v = 0.0;
#pragma unroll
    for (int h = 0; h < NH; h++) {
        int i = ibase + h * TPB;
        int ic = i < N_HITS ? i : N_HITS - 1;
        float qh = (i < N_HITS) ? compute_q(beta[ic]) : 0.f;
        int pown = (i < N_HITS) ? pid[ic] : 0;

        float total = 10.f * rsum[h];
        int c = pown - 1;                     // global cluster index
        int cl = c - hc * CPH;                // local within eighth
        if (pown > 0 && cl >= 0 && cl < CPH) {
            const float* cf = s_c + (cl >> 1) * 20 + (cl & 1);
            float acc = xsq[h] + cf[16];
            acc = fmaf(cf[0],  lo2(X[h][0]), acc);
            acc = fmaf(cf[2],  lo2(X[h][1]), acc);
            acc = fmaf(cf[4],  lo2(X[h][2]), acc);
            acc = fmaf(cf[6],  lo2(X[h][3]), acc);
            acc = fmaf(cf[8],  lo2(X[h][4]), acc);
            acc = fmaf(cf[10], lo2(X[h][5]), acc);
            acc = fmaf(cf[12], lo2(X[h][6]), acc);
            acc = fmaf(cf[14], lo2(X[h][7]), acc);
            acc = fmaxf(acc, 0.f);
            float dist = sqrtf(fmaxf(acc, 1e-12f));
            float hinge = fmaxf(1.f - dist, 0.f);
            total += (acc - 10.f * hinge) * s_q[cl];
        }
        v += (double)(qh * total);
    }

    // fp64 reduction: warp shuffle -> smem -> block -> one atomicAdd(double)
#pragma unroll
    for (int o = 16; o > 0; o >>= 1)
        v += __shfl_down_sync(0xffffffffu, v, o);

    __shared__ double s_part[TPB / 32];
    if ((threadIdx.x & 31) == 0) s_part[threadIdx.x >> 5] = v;
    __syncthreads();
    if (threadIdx.x == 0) {
        double w = 0.0;
#pragma unroll
        for (int k = 0; k < TPB / 32; k++) w += s_part[k];
        atomicAdd(&g_sum, w);
        // ---- last-block finalize ----
        if (atomicAdd(&g_done_m, 1) == (int)gridDim.x - 1) {
            double total = atomicAdd(&g_sum, 0.0);   // coherent read
            out[0] = (float)(total / (double)N_HITS);
            g_sum = 0.0;                              // reset for next replay
            g_done_m = 0;
        }
    }
}

// ---------------------------------------------------------------------------
// Launch: inputs in metadata order: w, beta, x, y, particle_id
// (w and y are unused by the reference loss)
// ---------------------------------------------------------------------------
extern "C" void kernel_launch(void* const* d_in, const int* in_sizes, int n_in,
                              void* d_out, int out_size) {
    const float* beta = (const float*)d_in[1];
    const float* x    = (const float*)d_in[2];
    const int*   pid  = (const int*)d_in[4];
    float* out = (float*)d_out;

    k_argmax<<<(N_HITS + ATPB - 1) / ATPB, ATPB>>>(beta, pid, x);
    k_main<<<NGRP * NSPLIT, TPB>>>(beta, x, pid, out);
}

// round 13
// speedup vs baseline: 1.7567x; 1.7567x over previous
#include <cuda_runtime.h>
#include <math.h>
#include <stdint.h>

// Problem constants (match reference_code)
#define N_HITS 200000
#define DIM 8
#define P_IDS 512
#define NCLUST 511          // nonzero particle ids 1..511
#define NPAIR 256           // 512 clusters (1 dummy pad) as 256 packed pairs
#define Q_MIN 0.01f

// ---------------------------------------------------------------------------
// Device scratch (no allocations allowed -> __device__ globals)
// ---------------------------------------------------------------------------
__device__ double g_sum;                           // static-init 0
__device__ unsigned long long g_best[P_IDS];       // packed (q_bits<<32)|(~idx)
__device__ int g_done_a;                           // block counter (argmax)
__device__ int g_done_m;                           // block counter (main)
// Pair-packed coefficients: pair j (clusters 2j, 2j+1), stride 20 floats:
//   float j*20 + 2*k + h : k=0..7 -> -2*xa_k ; k=8 -> |xa|^2 ; 18..19 unused
__device__ __align__(16) float g_pairc[NPAIR * 20];
__device__ float g_qa[P_IDS];                      // q_alpha per cluster (pad=0)

// ---------------------------------------------------------------------------
// Packed f32x2 helpers (sm_100+)
// ---------------------------------------------------------------------------
typedef unsigned long long u64;
__device__ __forceinline__ u64 fma2(u64 a, u64 b, u64 c) {
    u64 d;
    asm("fma.rn.f32x2 %0, %1, %2, %3;" : "=l"(d) : "l"(a), "l"(b), "l"(c));
    return d;
}
__device__ __forceinline__ u64 add2(u64 a, u64 b) {
    u64 d;
    asm("add.rn.f32x2 %0, %1, %2;" : "=l"(d) : "l"(a), "l"(b));
    return d;
}
__device__ __forceinline__ u64 bcast2(float x) {
    u64 r;
    asm("mov.b64 %0, {%1, %2};" : "=l"(r) : "f"(x), "f"(x));
    return r;
}
__device__ __forceinline__ void unpack2(u64 v, float& lo, float& hi) {
    asm("mov.b64 {%0, %1}, %2;" : "=f"(lo), "=f"(hi) : "l"(v));
}
__device__ __forceinline__ float lo2(u64 v) {
    float lo, hi;
    unpack2(v, lo, hi);
    return lo;
}
__device__ __forceinline__ u64 dbits(double d) { return __double_as_longlong(d); }

// Fast atanh: 0.5*ln((1+b)/(1-b)) via MUFU.LG2 + MUFU.RCP.
// beta in [0,1); rel err ~1e-6 -- far below the 1e-3 test threshold.
__device__ __forceinline__ float compute_q(float beta) {
    float r = __fdividef(1.0f + beta, 1.0f - beta);
    float a = 0.5f * __logf(r);
    return fmaf(a, a, Q_MIN);
}

// ---------------------------------------------------------------------------
// Kernel 1: per-cluster argmax of q. Two-stage: shared-memory atomicMax
// pre-aggregation per block, then one global atomicMax per touched cluster.
// The LAST block performs the representative gather (launch fusion).
// q >= 0.01 > 0 so float bits are monotone as unsigned; index complemented so
// q-ties pick the LOWER index (matches jnp.argmax). g_best==0 on entry
// (static init; re-zeroed in the gather phase each run).
// ---------------------------------------------------------------------------
#define ATPB 1024

__global__ __launch_bounds__(ATPB) void k_argmax(const float* __restrict__ beta,
                                                 const int* __restrict__ pid,
                                                 const float* __restrict__ x) {
    __shared__ unsigned long long s_best[P_IDS];      // 4 KB
    if (threadIdx.x < P_IDS) s_best[threadIdx.x] = 0ull;
    __syncthreads();

    int i = blockIdx.x * ATPB + threadIdx.x;
    if (i < N_HITS) {
        int p = pid[i];
        if (p != 0) {
            float q = compute_q(beta[i]);
            u64 packed = ((u64)__float_as_uint(q) << 32) |
                         (u64)(0xFFFFFFFFu - (unsigned)i);
            atomicMax(&s_best[p], packed);
        }
    }
    __syncthreads();

    // Flush touched clusters to global
    if (threadIdx.x > 0 && threadIdx.x < P_IDS) {
        u64 v = s_best[threadIdx.x];
        if (v != 0ull) atomicMax(&g_best[threadIdx.x], v);
    }

    // ---- last-block gather ----
    __threadfence();
    __syncthreads();
    __shared__ int s_last;
    if (threadIdx.x == 0)
        s_last = (atomicAdd(&g_done_a, 1) == (int)gridDim.x - 1);
    __syncthreads();
    if (!s_last) return;
    __threadfence();                                  // acquire

    if (threadIdx.x < P_IDS) {
        int p = threadIdx.x;                          // cluster idx 0..511
        int j = p >> 1, h = p & 1;
        float* dst = g_pairc + j * 20;
        if (p == NCLUST) {                            // dummy pad cluster
#pragma unroll
            for (int k = 0; k < 8; k++) dst[2 * k + h] = 0.f;
            dst[16 + h] = 1e30f;                      // huge b -> hinge never
            g_qa[p] = 0.f;
        } else {
            u64 packed = g_best[p + 1];
            g_best[p + 1] = 0ull;                     // reset for next replay
            int idx = (packed == 0ull)
                          ? 0
                          : (int)(0xFFFFFFFFu - (unsigned)(packed & 0xFFFFFFFFull));
            float b = 0.f;
#pragma unroll
            for (int k = 0; k < DIM; k++) {
                float v = x[idx * DIM + k];
                dst[2 * k + h] = -2.f * v;
                b = fmaf(v, v, b);
            }
            dst[16 + h] = b;
            g_qa[p] = compute_q(beta[idx]);
        }
    }
    if (threadIdx.x == 0) g_done_a = 0;               // reset counter
}

// ---------------------------------------------------------------------------
// Kernel 2: main loop. Grid = (hit groups) x (8 cluster eighths). R12 lesson:
// deferred rescan costs warp-level (40% of warps) -> keep the per-pair branch
// (slow path fires ~1.7% of warp-iters). This version makes the SCREEN nearly
// free: seed the FMA chain with (b - thr[h]) so the chain yields
// t' = b - 2x.xa - thr; hinge-active <=> sign(t'), and d^2 = t' + 1 (since
// xsq + thr = 1). Screen = OR of the four 32-bit halves' sign bits + one
// branch; the slow path reuses the live acc registers. Own-cluster fixup
// only in the owning eighth. LAST block finalizes.
// ---------------------------------------------------------------------------
#define TPB 128
#define NH 2
#define HPB (TPB * NH)          // 256 hits per group
#define NGRP ((N_HITS + HPB - 1) / HPB)   // 782
#define NSPLIT 8                // cluster eighths
#define PPH (NPAIR / NSPLIT)    // 32 pairs per eighth
#define CPH (P_IDS / NSPLIT)    // 64 clusters per eighth

__global__ __launch_bounds__(TPB) void k_main(const float* __restrict__ beta,
                                              const float* __restrict__ x,
                                              const int* __restrict__ pid,
                                              float* __restrict__ out) {
    __shared__ __align__(16) float s_c[PPH * 20];     // 2560 B
    __shared__ float s_q[CPH];                        // 256 B

    int grp = blockIdx.x >> 3;
    int hc  = blockIdx.x & 7;                         // cluster eighth 0..7
    {
        const float4* src = (const float4*)(g_pairc + hc * PPH * 20);
        float4* dst = (float4*)s_c;
        for (int t = threadIdx.x; t < PPH * 5; t += TPB) dst[t] = src[t];
        if (threadIdx.x < CPH) s_q[threadIdx.x] = g_qa[hc * CPH + threadIdx.x];
    }
    __syncthreads();

    int ibase = grp * HPB + threadIdx.x;
    float xsq[NH];
    u64 X[NH][8];     // broadcast-packed coords
    u64 NT[NH];       // broadcast-packed (-thr) = (xsq - 1)
#pragma unroll
    for (int h = 0; h < NH; h++) {
        int i = ibase + h * TPB;
        int ic = i < N_HITS ? i : N_HITS - 1;         // clamp tail
        float4 v0 = *(const float4*)(x + (size_t)ic * DIM);
        float4 v1 = *(const float4*)(x + (size_t)ic * DIM + 4);
        float s = v0.x * v0.x + v0.y * v0.y + v0.z * v0.z + v0.w * v0.w
                + v1.x * v1.x + v1.y * v1.y + v1.z * v1.z + v1.w * v1.w;
        xsq[h] = s;
        NT[h] = bcast2(s - 1.0f);                     // -thr = xsq - 1
        X[h][0] = bcast2(v0.x); X[h][1] = bcast2(v0.y);
        X[h][2] = bcast2(v0.z); X[h][3] = bcast2(v0.w);
        X[h][4] = bcast2(v1.x); X[h][5] = bcast2(v1.y);
        X[h][6] = bcast2(v1.z); X[h][7] = bcast2(v1.w);
    }

    float rsum[NH];
#pragma unroll
    for (int h = 0; h < NH; h++) rsum[h] = 0.f;

#pragma unroll 4
    for (int j = 0; j < PPH; j++) {
        const float* base = s_c + j * 20;
        double2 c01 = *(const double2*)(base);
        double2 c23 = *(const double2*)(base + 4);
        double2 c45 = *(const double2*)(base + 8);
        double2 c67 = *(const double2*)(base + 12);
        u64 bp = *(const u64*)(base + 16);

        u64 acc[NH];
#pragma unroll
        for (int h = 0; h < NH; h++) acc[h] = add2(bp, NT[h]);   // seed b - thr
#pragma unroll
        for (int h = 0; h < NH; h++) acc[h] = fma2(dbits(c01.x), X[h][0], acc[h]);
#pragma unroll
        for (int h = 0; h < NH; h++) acc[h] = fma2(dbits(c01.y), X[h][1], acc[h]);
#pragma unroll
        for (int h = 0; h < NH; h++) acc[h] = fma2(dbits(c23.x), X[h][2], acc[h]);
#pragma unroll
        for (int h = 0; h < NH; h++) acc[h] = fma2(dbits(c23.y), X[h][3], acc[h]);
#pragma unroll
        for (int h = 0; h < NH; h++) acc[h] = fma2(dbits(c45.x), X[h][4], acc[h]);
#pragma unroll
        for (int h = 0; h < NH; h++) acc[h] = fma2(dbits(c45.y), X[h][5], acc[h]);
#pragma unroll
        for (int h = 0; h < NH; h++) acc[h] = fma2(dbits(c67.x), X[h][6], acc[h]);
#pragma unroll
        for (int h = 0; h < NH; h++) acc[h] = fma2(dbits(c67.y), X[h][7], acc[h]);

        // Screen: any sign bit among the 4 packed t' values (t' < 0 <=> hinge)
        unsigned sg = (unsigned)acc[0] | (unsigned)(acc[0] >> 32) |
                      (unsigned)acc[1] | (unsigned)(acc[1] >> 32);
        if ((int)sg < 0) {                     // rare (~1.7% of warp-iters)
            float ql = s_q[2 * j], qr = s_q[2 * j + 1];
            float lo0, hi0, lo1, hi1;
            unpack2(acc[0], lo0, hi0);
            unpack2(acc[1], lo1, hi1);
            // d^2 = t' + 1; ref: dist = sqrt(max(max(d2,0), 1e-12))
            if (lo0 < 0.f)
                rsum[0] = fmaf(1.0f - sqrtf(fmaxf(lo0 + 1.0f, 1e-12f)), ql, rsum[0]);
            if (hi0 < 0.f)
                rsum[0] = fmaf(1.0f - sqrtf(fmaxf(hi0 + 1.0f, 1e-12f)), qr, rsum[0]);
            if (lo1 < 0.f)
                rsum[1] = fmaf(1.0f - sqrtf(fmaxf(lo1 + 1.0f, 1e-12f)), ql, rsum[1]);
            if (hi1 < 0.f)
                rsum[1] = fmaf(1.0f - sqrtf(fmaxf(hi1 + 1.0f, 1e-12f)), qr, rsum[1]);
        }
    }

    // Per-hit q / pid loaded AFTER the hot loop (lower live-reg pressure)
    double v = 0.0;
#pragma unroll
    for (int h = 0; h < NH; h++) {
        int i = ibase + h * TPB;
        int ic = i < N_HITS ? i : N_HITS - 1;
        float qh = (i < N_HITS) ? compute_q(beta[ic]) : 0.f;
        int pown = (i < N_HITS) ? pid[ic] : 0;

        float total = 10.f * rsum[h];
        int c = pown - 1;                     // global cluster index
        int cl = c - hc * CPH;                // local within eighth
        if (pown > 0 && cl >= 0 && cl < CPH) {
            const float* cf = s_c + (cl >> 1) * 20 + (cl & 1);
            float acc = xsq[h] + cf[16];
            acc = fmaf(cf[0],  lo2(X[h][0]), acc);
            acc = fmaf(cf[2],  lo2(X[h][1]), acc);
            acc = fmaf(cf[4],  lo2(X[h][2]), acc);
            acc = fmaf(cf[6],  lo2(X[h][3]), acc);
            acc = fmaf(cf[8],  lo2(X[h][4]), acc);
            acc = fmaf(cf[10], lo2(X[h][5]), acc);
            acc = fmaf(cf[12], lo2(X[h][6]), acc);
            acc = fmaf(cf[14], lo2(X[h][7]), acc);
            acc = fmaxf(acc, 0.f);
            float dist = sqrtf(fmaxf(acc, 1e-12f));
            float hinge = fmaxf(1.f - dist, 0.f);
            total += (acc - 10.f * hinge) * s_q[cl];
        }
        v += (double)(qh * total);
    }

    // fp64 reduction: warp shuffle -> smem -> block -> one atomicAdd(double)
#pragma unroll
    for (int o = 16; o > 0; o >>= 1)
        v += __shfl_down_sync(0xffffffffu, v, o);

    __shared__ double s_part[TPB / 32];
    if ((threadIdx.x & 31) == 0) s_part[threadIdx.x >> 5] = v;
    __syncthreads();
    if (threadIdx.x == 0) {
        double w = 0.0;
#pragma unroll
        for (int k = 0; k < TPB / 32; k++) w += s_part[k];
        atomicAdd(&g_sum, w);
        // ---- last-block finalize ----
        if (atomicAdd(&g_done_m, 1) == (int)gridDim.x - 1) {
            double total = atomicAdd(&g_sum, 0.0);   // coherent read
            out[0] = (float)(total / (double)N_HITS);
            g_sum = 0.0;                              // reset for next replay
            g_done_m = 0;
        }
    }
}

// ---------------------------------------------------------------------------
// Launch: inputs in metadata order: w, beta, x, y, particle_id
// (w and y are unused by the reference loss)
// ---------------------------------------------------------------------------
extern "C" void kernel_launch(void* const* d_in, const int* in_sizes, int n_in,
                              void* d_out, int out_size) {
    const float* beta = (const float*)d_in[1];
    const float* x    = (const float*)d_in[2];
    const int*   pid  = (const int*)d_in[4];
    float* out = (float*)d_out;

    k_argmax<<<(N_HITS + ATPB - 1) / ATPB, ATPB>>>(beta, pid, x);
    k_main<<<NGRP * NSPLIT, TPB>>>(beta, x, pid, out);
}

// round 15
// speedup vs baseline: 1.7924x; 1.0203x over previous
#include <cuda_runtime.h>
#include <math.h>
#include <stdint.h>

// Problem constants (match reference_code)
#define N_HITS 200000
#define DIM 8
#define P_IDS 512
#define NCLUST 511          // nonzero particle ids 1..511
#define NPAIR 256           // 512 clusters (1 dummy pad) as 256 packed pairs
#define Q_MIN 0.01f

// ---------------------------------------------------------------------------
// Device scratch (no allocations allowed -> __device__ globals)
// ---------------------------------------------------------------------------
__device__ double g_sum;                           // static-init 0
__device__ unsigned long long g_best[P_IDS];       // packed (q_bits<<32)|(~idx)
__device__ int g_done_a;                           // block counter (argmax)
__device__ int g_done_m;                           // block counter (main)
// Pair-packed coefficients: pair j (clusters 2j, 2j+1), stride 20 floats:
//   float j*20 + 2*k + h : k=0..7 -> -2*xa_k ; k=8 -> |xa|^2 ; 18..19 unused
__device__ __align__(16) float g_pairc[NPAIR * 20];
__device__ float g_qa[P_IDS];                      // q_alpha per cluster (pad=0)

// ---------------------------------------------------------------------------
// Packed f32x2 helpers (sm_100+)
// ---------------------------------------------------------------------------
typedef unsigned long long u64;
__device__ __forceinline__ u64 fma2(u64 a, u64 b, u64 c) {
    u64 d;
    asm("fma.rn.f32x2 %0, %1, %2, %3;" : "=l"(d) : "l"(a), "l"(b), "l"(c));
    return d;
}
__device__ __forceinline__ u64 add2(u64 a, u64 b) {
    u64 d;
    asm("add.rn.f32x2 %0, %1, %2;" : "=l"(d) : "l"(a), "l"(b));
    return d;
}
__device__ __forceinline__ u64 bcast2(float x) {
    u64 r;
    asm("mov.b64 %0, {%1, %2};" : "=l"(r) : "f"(x), "f"(x));
    return r;
}
__device__ __forceinline__ void unpack2(u64 v, float& lo, float& hi) {
    asm("mov.b64 {%0, %1}, %2;" : "=f"(lo), "=f"(hi) : "l"(v));
}
__device__ __forceinline__ float lo2(u64 v) {
    float lo, hi;
    unpack2(v, lo, hi);
    return lo;
}
__device__ __forceinline__ u64 dbits(double d) { return __double_as_longlong(d); }

// Fast atanh: 0.5*ln((1+b)/(1-b)) via MUFU.LG2 + MUFU.RCP.
// beta in [0,1); rel err ~1e-6 -- far below the 1e-3 test threshold.
__device__ __forceinline__ float compute_q(float beta) {
    float r = __fdividef(1.0f + beta, 1.0f - beta);
    float a = 0.5f * __logf(r);
    return fmaf(a, a, Q_MIN);
}

// ---------------------------------------------------------------------------
// Kernel 1: per-cluster argmax of q. Two-stage: shared-memory atomicMax
// pre-aggregation per block, then one global atomicMax per touched cluster.
// The LAST block performs the representative gather (launch fusion).
// q >= 0.01 > 0 so float bits are monotone as unsigned; index complemented so
// q-ties pick the LOWER index (matches jnp.argmax). g_best==0 on entry
// (static init; re-zeroed in the gather phase each run).
// ---------------------------------------------------------------------------
#define ATPB 1024

__global__ __launch_bounds__(ATPB) void k_argmax(const float* __restrict__ beta,
                                                 const int* __restrict__ pid,
                                                 const float* __restrict__ x) {
    __shared__ unsigned long long s_best[P_IDS];      // 4 KB
    if (threadIdx.x < P_IDS) s_best[threadIdx.x] = 0ull;
    __syncthreads();

    int i = blockIdx.x * ATPB + threadIdx.x;
    if (i < N_HITS) {
        int p = pid[i];
        if (p != 0) {
            float q = compute_q(beta[i]);
            u64 packed = ((u64)__float_as_uint(q) << 32) |
                         (u64)(0xFFFFFFFFu - (unsigned)i);
            atomicMax(&s_best[p], packed);
        }
    }
    __syncthreads();

    // Flush touched clusters to global
    if (threadIdx.x > 0 && threadIdx.x < P_IDS) {
        u64 v = s_best[threadIdx.x];
        if (v != 0ull) atomicMax(&g_best[threadIdx.x], v);
    }

    // ---- last-block gather ----
    __threadfence();
    __syncthreads();
    __shared__ int s_last;
    if (threadIdx.x == 0)
        s_last = (atomicAdd(&g_done_a, 1) == (int)gridDim.x - 1);
    __syncthreads();
    if (!s_last) return;
    __threadfence();                                  // acquire

    if (threadIdx.x < P_IDS) {
        int p = threadIdx.x;                          // cluster idx 0..511
        int j = p >> 1, h = p & 1;
        float* dst = g_pairc + j * 20;
        if (p == NCLUST) {                            // dummy pad cluster
#pragma unroll
            for (int k = 0; k < 8; k++) dst[2 * k + h] = 0.f;
            dst[16 + h] = 1e30f;                      // huge b -> hinge never
            g_qa[p] = 0.f;
        } else {
            u64 packed = g_best[p + 1];
            g_best[p + 1] = 0ull;                     // reset for next replay
            int idx = (packed == 0ull)
                          ? 0
                          : (int)(0xFFFFFFFFu - (unsigned)(packed & 0xFFFFFFFFull));
            float b = 0.f;
#pragma unroll
            for (int k = 0; k < DIM; k++) {
                float v = x[idx * DIM + k];
                dst[2 * k + h] = -2.f * v;
                b = fmaf(v, v, b);
            }
            dst[16 + h] = b;
            g_qa[p] = compute_q(beta[idx]);
        }
    }
    if (threadIdx.x == 0) g_done_a = 0;               // reset counter
}

// ---------------------------------------------------------------------------
// Kernel 2: main loop. Grid = (hit groups) x (8 cluster eighths). R13 lesson:
// fma-pipe busy (27.5us) matches rt-2 accounting exactly, but utilization is
// pinned ~53% because the per-iteration screen BRANCH depends on the
// just-computed FMA chain -> the warp stalls at the branch every iteration
// (useful/(useful+wait) ~ 51%, matching). Fix: SOFTWARE-PIPELINE the screen
// by one iteration -- branch on the PREVIOUS pair's sign flags (resolved
// long ago, zero stall) while the current chains are in flight. Slow path
// stays per-pair (R12 lesson: end-deferral is warp-level catastrophic).
// Chain seeded with (b - thr): t' < 0 <=> hinge active; d^2 = t' + 1.
// Own-cluster fixup only in the owning eighth. LAST block finalizes.
// ---------------------------------------------------------------------------
#define TPB 128
#define NH 2
#define HPB (TPB * NH)          // 256 hits per group
#define NGRP ((N_HITS + HPB - 1) / HPB)   // 782
#define NSPLIT 8                // cluster eighths
#define PPH (NPAIR / NSPLIT)    // 32 pairs per eighth
#define CPH (P_IDS / NSPLIT)    // 64 clusters per eighth

__global__ __launch_bounds__(TPB) void k_main(const float* __restrict__ beta,
                                              const float* __restrict__ x,
                                              const int* __restrict__ pid,
                                              float* __restrict__ out) {
    __shared__ __align__(16) float s_c[PPH * 20];     // 2560 B
    __shared__ float s_q[CPH];                        // 256 B

    int grp = blockIdx.x >> 3;
    int hc  = blockIdx.x & 7;                         // cluster eighth 0..7
    {
        const float4* src = (const float4*)(g_pairc + hc * PPH * 20);
        float4* dst = (float4*)s_c;
        for (int t = threadIdx.x; t < PPH * 5; t += TPB) dst[t] = src[t];
        if (threadIdx.x < CPH) s_q[threadIdx.x] = g_qa[hc * CPH + threadIdx.x];
    }
    __syncthreads();

    int ibase = grp * HPB + threadIdx.x;
    float xsq[NH];
    u64 X[NH][8];     // broadcast-packed coords
    u64 NT[NH];       // broadcast-packed (-thr) = (xsq - 1)
#pragma unroll
    for (int h = 0; h < NH; h++) {
        int i = ibase + h * TPB;
        int ic = i < N_HITS ? i : N_HITS - 1;         // clamp tail
        float4 v0 = *(const float4*)(x + (size_t)ic * DIM);
        float4 v1 = *(const float4*)(x + (size_t)ic * DIM + 4);
        float s = v0.x * v0.x + v0.y * v0.y + v0.z * v0.z + v0.w * v0.w
                + v1.x * v1.x + v1.y * v1.y + v1.z * v1.z + v1.w * v1.w;
        xsq[h] = s;
        NT[h] = bcast2(s - 1.0f);                     // -thr = xsq - 1
        X[h][0] = bcast2(v0.x); X[h][1] = bcast2(v0.y);
        X[h][2] = bcast2(v0.z); X[h][3] = bcast2(v0.w);
        X[h][4] = bcast2(v1.x); X[h][5] = bcast2(v1.y);
        X[h][6] = bcast2(v1.z); X[h][7] = bcast2(v1.w);
    }

    float rsum[NH];
#pragma unroll
    for (int h = 0; h < NH; h++) rsum[h] = 0.f;

    // Software-pipelined screen: pa0/pa1 hold the PREVIOUS pair's t' values.
    u64 pa0 = bcast2(1.0f), pa1 = bcast2(1.0f);       // positive: no slow path
    int pj = 0;                                       // previous pair index

#pragma unroll 4
    for (int j = 0; j < PPH; j++) {
        const float* base = s_c + j * 20;
        double2 c01 = *(const double2*)(base);
        double2 c23 = *(const double2*)(base + 4);
        double2 c45 = *(const double2*)(base + 8);
        double2 c67 = *(const double2*)(base + 12);
        u64 bp = *(const u64*)(base + 16);

        u64 a0 = add2(bp, NT[0]);                     // seed b - thr
        u64 a1 = add2(bp, NT[1]);
        a0 = fma2(dbits(c01.x), X[0][0], a0);  a1 = fma2(dbits(c01.x), X[1][0], a1);
        a0 = fma2(dbits(c01.y), X[0][1], a0);  a1 = fma2(dbits(c01.y), X[1][1], a1);
        a0 = fma2(dbits(c23.x), X[0][2], a0);  a1 = fma2(dbits(c23.x), X[1][2], a1);
        a0 = fma2(dbits(c23.y), X[0][3], a0);  a1 = fma2(dbits(c23.y), X[1][3], a1);
        a0 = fma2(dbits(c45.x), X[0][4], a0);  a1 = fma2(dbits(c45.x), X[1][4], a1);
        a0 = fma2(dbits(c45.y), X[0][5], a0);  a1 = fma2(dbits(c45.y), X[1][5], a1);
        a0 = fma2(dbits(c67.x), X[0][6], a0);  a1 = fma2(dbits(c67.x), X[1][6], a1);
        a0 = fma2(dbits(c67.y), X[0][7], a0);  a1 = fma2(dbits(c67.y), X[1][7], a1);

        // Screen the PREVIOUS pair (registers resolved long ago -> no stall)
        unsigned sg = (unsigned)pa0 | (unsigned)(pa0 >> 32) |
                      (unsigned)pa1 | (unsigned)(pa1 >> 32);
        if ((int)sg < 0) {                     // rare (~1.7% of warp-iters)
            float ql = s_q[2 * pj], qr = s_q[2 * pj + 1];
            float lo0, hi0, lo1, hi1;
            unpack2(pa0, lo0, hi0);
            unpack2(pa1, lo1, hi1);
            // d^2 = t' + 1; ref: dist = sqrt(max(max(d2,0), 1e-12))
            if (lo0 < 0.f)
                rsum[0] = fmaf(1.0f - sqrtf(fmaxf(lo0 + 1.0f, 1e-12f)), ql, rsum[0]);
            if (hi0 < 0.f)
                rsum[0] = fmaf(1.0f - sqrtf(fmaxf(hi0 + 1.0f, 1e-12f)), qr, rsum[0]);
            if (lo1 < 0.f)
                rsum[1] = fmaf(1.0f - sqrtf(fmaxf(lo1 + 1.0f, 1e-12f)), ql, rsum[1]);
            if (hi1 < 0.f)
                rsum[1] = fmaf(1.0f - sqrtf(fmaxf(hi1 + 1.0f, 1e-12f)), qr, rsum[1]);
        }
        pa0 = a0; pa1 = a1; pj = j;
    }

    // Drain the final pair's deferred screen
    {
        unsigned sg = (unsigned)pa0 | (unsigned)(pa0 >> 32) |
                      (unsigned)pa1 | (unsigned)(pa1 >> 32);
        if ((int)sg < 0) {
            float ql = s_q[2 * pj], qr = s_q[2 * pj + 1];
            float lo0, hi0, lo1, hi1;
            unpack2(pa0, lo0, hi0);
            unpack2(pa1, lo1, hi1);
            if (lo0 < 0.f)
                rsum[0] = fmaf(1.0f - sqrtf(fmaxf(lo0 + 1.0f, 1e-12f)), ql, rsum[0]);
            if (hi0 < 0.f)
                rsum[0] = fmaf(1.0f - sqrtf(fmaxf(hi0 + 1.0f, 1e-12f)), qr, rsum[0]);
            if (lo1 < 0.f)
                rsum[1] = fmaf(1.0f - sqrtf(fmaxf(lo1 + 1.0f, 1e-12f)), ql, rsum[1]);
            if (hi1 < 0.f)
                rsum[1] = fmaf(1.0f - sqrtf(fmaxf(hi1 + 1.0f, 1e-12f)), qr, rsum[1]);
        }
    }

    // Per-hit q / pid loaded AFTER the hot loop (lower live-reg pressure)
    double v = 0.0;
#pragma unroll
    for (int h = 0; h < NH; h++) {
        int i = ibase + h * TPB;
        int ic = i < N_HITS ? i : N_HITS - 1;
        float qh = (i < N_HITS) ? compute_q(beta[ic]) : 0.f;
        int pown = (i < N_HITS) ? pid[ic] : 0;

        float total = 10.f * rsum[h];
        int c = pown - 1;                     // global cluster index
        int cl = c - hc * CPH;                // local within eighth
        if (pown > 0 && cl >= 0 && cl < CPH) {
            const float* cf = s_c + (cl >> 1) * 20 + (cl & 1);
            float acc = xsq[h] + cf[16];
            acc = fmaf(cf[0],  lo2(X[h][0]), acc);
            acc = fmaf(cf[2],  lo2(X[h][1]), acc);
            acc = fmaf(cf[4],  lo2(X[h][2]), acc);
            acc = fmaf(cf[6],  lo2(X[h][3]), acc);
            acc = fmaf(cf[8],  lo2(X[h][4]), acc);
            acc = fmaf(cf[10], lo2(X[h][5]), acc);
            acc = fmaf(cf[12], lo2(X[h][6]), acc);
            acc = fmaf(cf[14], lo2(X[h][7]), acc);
            acc = fmaxf(acc, 0.f);
            float dist = sqrtf(fmaxf(acc, 1e-12f));
            float hinge = fmaxf(1.f - dist, 0.f);
            total += (acc - 10.f * hinge) * s_q[cl];
        }
        v += (double)(qh * total);
    }

    // fp64 reduction: warp shuffle -> smem -> block -> one atomicAdd(double)
#pragma unroll
    for (int o = 16; o > 0; o >>= 1)
        v += __shfl_down_sync(0xffffffffu, v, o);

    __shared__ double s_part[TPB / 32];
    if ((threadIdx.x & 31) == 0) s_part[threadIdx.x >> 5] = v;
    __syncthreads();
    if (threadIdx.x == 0) {
        double w = 0.0;
#pragma unroll
        for (int k = 0; k < TPB / 32; k++) w += s_part[k];
        atomicAdd(&g_sum, w);
        // ---- last-block finalize ----
        if (atomicAdd(&g_done_m, 1) == (int)gridDim.x - 1) {
            double total = atomicAdd(&g_sum, 0.0);   // coherent read
            out[0] = (float)(total / (double)N_HITS);
            g_sum = 0.0;                              // reset for next replay
            g_done_m = 0;
        }
    }
}

// ---------------------------------------------------------------------------
// Launch: inputs in metadata order: w, beta, x, y, particle_id
// (w and y are unused by the reference loss)
// ---------------------------------------------------------------------------
extern "C" void kernel_launch(void* const* d_in, const int* in_sizes, int n_in,
                              void* d_out, int out_size) {
    const float* beta = (const float*)d_in[1];
    const float* x    = (const float*)d_in[2];
    const int*   pid  = (const int*)d_in[4];
    float* out = (float*)d_out;

    k_argmax<<<(N_HITS + ATPB - 1) / ATPB, ATPB>>>(beta, pid, x);
    k_main<<<NGRP * NSPLIT, TPB>>>(beta, x, pid, out);
}

// round 16
// speedup vs baseline: 1.8214x; 1.0162x over previous
#include <cuda_runtime.h>
#include <math.h>
#include <stdint.h>

// Problem constants (match reference_code)
#define N_HITS 200000
#define DIM 8
#define P_IDS 512
#define NCLUST 511          // nonzero particle ids 1..511
#define NPAIR 256           // 512 clusters (1 dummy pad) as 256 packed pairs
#define Q_MIN 0.01f

// ---------------------------------------------------------------------------
// Device scratch (no allocations allowed -> __device__ globals)
// ---------------------------------------------------------------------------
__device__ double g_sum;                           // static-init 0
__device__ unsigned long long g_best[P_IDS];       // packed (q_bits<<32)|(~idx)
__device__ int g_done_a;                           // block counter (argmax)
__device__ int g_done_m;                           // block counter (main)
// Pair-packed coefficients: pair j (clusters 2j, 2j+1), stride 20 floats:
//   float j*20 + 2*k + h : k=0..7 -> -2*xa_k ; k=8 -> |xa|^2 ; 18..19 unused
__device__ __align__(16) float g_pairc[NPAIR * 20];
__device__ float g_qa[P_IDS];                      // q_alpha per cluster (pad=0)

// ---------------------------------------------------------------------------
// Packed f32x2 helpers (sm_100+)
// ---------------------------------------------------------------------------
typedef unsigned long long u64;
__device__ __forceinline__ u64 fma2(u64 a, u64 b, u64 c) {
    u64 d;
    asm("fma.rn.f32x2 %0, %1, %2, %3;" : "=l"(d) : "l"(a), "l"(b), "l"(c));
    return d;
}
__device__ __forceinline__ u64 add2(u64 a, u64 b) {
    u64 d;
    asm("add.rn.f32x2 %0, %1, %2;" : "=l"(d) : "l"(a), "l"(b));
    return d;
}
__device__ __forceinline__ u64 bcast2(float x) {
    u64 r;
    asm("mov.b64 %0, {%1, %2};" : "=l"(r) : "f"(x), "f"(x));
    return r;
}
__device__ __forceinline__ void unpack2(u64 v, float& lo, float& hi) {
    asm("mov.b64 {%0, %1}, %2;" : "=f"(lo), "=f"(hi) : "l"(v));
}
__device__ __forceinline__ float lo2(u64 v) {
    float lo, hi;
    unpack2(v, lo, hi);
    return lo;
}
__device__ __forceinline__ u64 dbits(double d) { return __double_as_longlong(d); }

// Fast atanh: 0.5*ln((1+b)/(1-b)) via MUFU.LG2 + MUFU.RCP.
// beta in [0,1); rel err ~1e-6 -- far below the 1e-3 test threshold.
__device__ __forceinline__ float compute_q(float beta) {
    float r = __fdividef(1.0f + beta, 1.0f - beta);
    float a = 0.5f * __logf(r);
    return fmaf(a, a, Q_MIN);
}

// ---------------------------------------------------------------------------
// Kernel 1: per-cluster argmax of q. Two-stage: shared-memory atomicMax
// pre-aggregation per block, then one global atomicMax per touched cluster.
// The LAST block performs the representative gather (launch fusion).
// q >= 0.01 > 0 so float bits are monotone as unsigned; index complemented so
// q-ties pick the LOWER index (matches jnp.argmax). g_best==0 on entry
// (static init; re-zeroed in the gather phase each run).
// ---------------------------------------------------------------------------
#define ATPB 1024

__global__ __launch_bounds__(ATPB) void k_argmax(const float* __restrict__ beta,
                                                 const int* __restrict__ pid,
                                                 const float* __restrict__ x) {
    __shared__ unsigned long long s_best[P_IDS];      // 4 KB
    if (threadIdx.x < P_IDS) s_best[threadIdx.x] = 0ull;
    __syncthreads();

    int i = blockIdx.x * ATPB + threadIdx.x;
    if (i < N_HITS) {
        int p = pid[i];
        if (p != 0) {
            float q = compute_q(beta[i]);
            u64 packed = ((u64)__float_as_uint(q) << 32) |
                         (u64)(0xFFFFFFFFu - (unsigned)i);
            atomicMax(&s_best[p], packed);
        }
    }
    __syncthreads();

    // Flush touched clusters to global
    if (threadIdx.x > 0 && threadIdx.x < P_IDS) {
        u64 v = s_best[threadIdx.x];
        if (v != 0ull) atomicMax(&g_best[threadIdx.x], v);
    }

    // ---- last-block gather ----
    __threadfence();
    __syncthreads();
    __shared__ int s_last;
    if (threadIdx.x == 0)
        s_last = (atomicAdd(&g_done_a, 1) == (int)gridDim.x - 1);
    __syncthreads();
    if (!s_last) return;
    __threadfence();                                  // acquire

    if (threadIdx.x < P_IDS) {
        int p = threadIdx.x;                          // cluster idx 0..511
        int j = p >> 1, h = p & 1;
        float* dst = g_pairc + j * 20;
        if (p == NCLUST) {                            // dummy pad cluster
#pragma unroll
            for (int k = 0; k < 8; k++) dst[2 * k + h] = 0.f;
            dst[16 + h] = 1e30f;                      // huge b -> hinge never
            g_qa[p] = 0.f;
        } else {
            u64 packed = g_best[p + 1];
            g_best[p + 1] = 0ull;                     // reset for next replay
            int idx = (packed == 0ull)
                          ? 0
                          : (int)(0xFFFFFFFFu - (unsigned)(packed & 0xFFFFFFFFull));
            float b = 0.f;
#pragma unroll
            for (int k = 0; k < DIM; k++) {
                float v = x[idx * DIM + k];
                dst[2 * k + h] = -2.f * v;
                b = fmaf(v, v, b);
            }
            dst[16 + h] = b;
            g_qa[p] = compute_q(beta[idx]);
        }
    }
    if (threadIdx.x == 0) g_done_a = 0;               // reset counter
}

// ---------------------------------------------------------------------------
// Kernel 2: main loop. Grid = (hit groups) x (8 cluster eighths). R6-R15
// lesson: k_main pinned 50-53us under EVERY scheduling change at NH=2 -> the
// invariant is 2 independent FMA chains/thread. This round: NH=4 (4 chains,
// 2x ILP) at a healthy grid (3128 blocks; R5's NH=4 failed on grid size, not
// ILP). Per iter: 5 LDS + 4 add2 + 32 fma2 (77% fma share). Screen = sign-OR
// over the 4 packed t' accs + one branch (slow path ~3%/warp-iter). Chain
// seeded with (b - thr): t' < 0 <=> hinge active; d^2 = t' + 1. Occupancy
// drops to ~25% -- demonstrated irrelevant over 44-75%. LAST block finalizes.
// ---------------------------------------------------------------------------
#define TPB 128
#define NH 4
#define HPB (TPB * NH)          // 512 hits per group
#define NGRP ((N_HITS + HPB - 1) / HPB)   // 391
#define NSPLIT 8                // cluster eighths
#define PPH (NPAIR / NSPLIT)    // 32 pairs per eighth
#define CPH (P_IDS / NSPLIT)    // 64 clusters per eighth

__global__ __launch_bounds__(TPB) void k_main(const float* __restrict__ beta,
                                              const float* __restrict__ x,
                                              const int* __restrict__ pid,
                                              float* __restrict__ out) {
    __shared__ __align__(16) float s_c[PPH * 20];     // 2560 B
    __shared__ float s_q[CPH];                        // 256 B

    int grp = blockIdx.x >> 3;
    int hc  = blockIdx.x & 7;                         // cluster eighth 0..7
    {
        const float4* src = (const float4*)(g_pairc + hc * PPH * 20);
        float4* dst = (float4*)s_c;
        for (int t = threadIdx.x; t < PPH * 5; t += TPB) dst[t] = src[t];
        if (threadIdx.x < CPH) s_q[threadIdx.x] = g_qa[hc * CPH + threadIdx.x];
    }
    __syncthreads();

    int ibase = grp * HPB + threadIdx.x;
    float xsq[NH];
    u64 X[NH][8];     // broadcast-packed coords
    u64 NT[NH];       // broadcast-packed (-thr) = (xsq - 1)
#pragma unroll
    for (int h = 0; h < NH; h++) {
        int i = ibase + h * TPB;
        int ic = i < N_HITS ? i : N_HITS - 1;         // clamp tail
        float4 v0 = *(const float4*)(x + (size_t)ic * DIM);
        float4 v1 = *(const float4*)(x + (size_t)ic * DIM + 4);
        float s = v0.x * v0.x + v0.y * v0.y + v0.z * v0.z + v0.w * v0.w
                + v1.x * v1.x + v1.y * v1.y + v1.z * v1.z + v1.w * v1.w;
        xsq[h] = s;
        NT[h] = bcast2(s - 1.0f);                     // -thr = xsq - 1
        X[h][0] = bcast2(v0.x); X[h][1] = bcast2(v0.y);
        X[h][2] = bcast2(v0.z); X[h][3] = bcast2(v0.w);
        X[h][4] = bcast2(v1.x); X[h][5] = bcast2(v1.y);
        X[h][6] = bcast2(v1.z); X[h][7] = bcast2(v1.w);
    }

    float rsum[NH];
#pragma unroll
    for (int h = 0; h < NH; h++) rsum[h] = 0.f;

#pragma unroll 2
    for (int j = 0; j < PPH; j++) {
        const float* base = s_c + j * 20;
        double2 c01 = *(const double2*)(base);
        double2 c23 = *(const double2*)(base + 4);
        double2 c45 = *(const double2*)(base + 8);
        double2 c67 = *(const double2*)(base + 12);
        u64 bp = *(const u64*)(base + 16);

        u64 acc[NH];
#pragma unroll
        for (int h = 0; h < NH; h++) acc[h] = add2(bp, NT[h]);   // seed b - thr
#pragma unroll
        for (int h = 0; h < NH; h++) acc[h] = fma2(dbits(c01.x), X[h][0], acc[h]);
#pragma unroll
        for (int h = 0; h < NH; h++) acc[h] = fma2(dbits(c01.y), X[h][1], acc[h]);
#pragma unroll
        for (int h = 0; h < NH; h++) acc[h] = fma2(dbits(c23.x), X[h][2], acc[h]);
#pragma unroll
        for (int h = 0; h < NH; h++) acc[h] = fma2(dbits(c23.y), X[h][3], acc[h]);
#pragma unroll
        for (int h = 0; h < NH; h++) acc[h] = fma2(dbits(c45.x), X[h][4], acc[h]);
#pragma unroll
        for (int h = 0; h < NH; h++) acc[h] = fma2(dbits(c45.y), X[h][5], acc[h]);
#pragma unroll
        for (int h = 0; h < NH; h++) acc[h] = fma2(dbits(c67.x), X[h][6], acc[h]);
#pragma unroll
        for (int h = 0; h < NH; h++) acc[h] = fma2(dbits(c67.y), X[h][7], acc[h]);

        // Screen: any sign bit among the 8 packed t' halves (t' < 0 <=> hinge)
        u64 m64 = acc[0] | acc[1] | acc[2] | acc[3];
        unsigned sg = (unsigned)m64 | (unsigned)(m64 >> 32);
        if ((int)sg < 0) {                     // rare (~3% of warp-iters)
            float ql = s_q[2 * j], qr = s_q[2 * j + 1];
#pragma unroll
            for (int h = 0; h < NH; h++) {
                float lo, hi;
                unpack2(acc[h], lo, hi);
                // d^2 = t' + 1; ref: dist = sqrt(max(max(d2,0), 1e-12))
                if (lo < 0.f)
                    rsum[h] = fmaf(1.0f - sqrtf(fmaxf(lo + 1.0f, 1e-12f)), ql, rsum[h]);
                if (hi < 0.f)
                    rsum[h] = fmaf(1.0f - sqrtf(fmaxf(hi + 1.0f, 1e-12f)), qr, rsum[h]);
            }
        }
    }

    // Per-hit q / pid loaded AFTER the hot loop (lower live-reg pressure)
    double v = 0.0;
#pragma unroll
    for (int h = 0; h < NH; h++) {
        int i = ibase + h * TPB;
        int ic = i < N_HITS ? i : N_HITS - 1;
        float qh = (i < N_HITS) ? compute_q(beta[ic]) : 0.f;
        int pown = (i < N_HITS) ? pid[ic] : 0;

        float total = 10.f * rsum[h];
        int c = pown - 1;                     // global cluster index
        int cl = c - hc * CPH;                // local within eighth
        if (pown > 0 && cl >= 0 && cl < CPH) {
            const float* cf = s_c + (cl >> 1) * 20 + (cl & 1);
            float acc = xsq[h] + cf[16];
            acc = fmaf(cf[0],  lo2(X[h][0]), acc);
            acc = fmaf(cf[2],  lo2(X[h][1]), acc);
            acc = fmaf(cf[4],  lo2(X[h][2]), acc);
            acc = fmaf(cf[6],  lo2(X[h][3]), acc);
            acc = fmaf(cf[8],  lo2(X[h][4]), acc);
            acc = fmaf(cf[10], lo2(X[h][5]), acc);
            acc = fmaf(cf[12], lo2(X[h][6]), acc);
            acc = fmaf(cf[14], lo2(X[h][7]), acc);
            acc = fmaxf(acc, 0.f);
            float dist = sqrtf(fmaxf(acc, 1e-12f));
            float hinge = fmaxf(1.f - dist, 0.f);
            total += (acc - 10.f * hinge) * s_q[cl];
        }
        v += (double)(qh * total);
    }

    // fp64 reduction: warp shuffle -> smem -> block -> one atomicAdd(double)
#pragma unroll
    for (int o = 16; o > 0; o >>= 1)
        v += __shfl_down_sync(0xffffffffu, v, o);

    __shared__ double s_part[TPB / 32];
    if ((threadIdx.x & 31) == 0) s_part[threadIdx.x >> 5] = v;
    __syncthreads();
    if (threadIdx.x == 0) {
        double w = 0.0;
#pragma unroll
        for (int k = 0; k < TPB / 32; k++) w += s_part[k];
        atomicAdd(&g_sum, w);
        // ---- last-block finalize ----
        if (atomicAdd(&g_done_m, 1) == (int)gridDim.x - 1) {
            double total = atomicAdd(&g_sum, 0.0);   // coherent read
            out[0] = (float)(total / (double)N_HITS);
            g_sum = 0.0;                              // reset for next replay
            g_done_m = 0;
        }
    }
}

// ---------------------------------------------------------------------------
// Launch: inputs in metadata order: w, beta, x, y, particle_id
// (w and y are unused by the reference loss)
// ---------------------------------------------------------------------------
extern "C" void kernel_launch(void* const* d_in, const int* in_sizes, int n_in,
                              void* d_out, int out_size) {
    const float* beta = (const float*)d_in[1];
    const float* x    = (const float*)d_in[2];
    const int*   pid  = (const int*)d_in[4];
    float* out = (float*)d_out;

    k_argmax<<<(N_HITS + ATPB - 1) / ATPB, ATPB>>>(beta, pid, x);
    k_main<<<NGRP * NSPLIT, TPB>>>(beta, x, pid, out);
}